// round 5
// baseline (speedup 1.0000x reference)
#include <cuda_runtime.h>
#include <math.h>

#define BB 1024
#define SS 200
#define DD 64
#define NI 4
#define AS 224   // padded S for adj tiling

// ---------------- scratch (__device__ globals: allocation-free) ----------------
__device__ float g_user_buf[BB * DD];
__device__ float g_hat_buf[(size_t)BB * NI * SS * DD];   // [b][k][s][d], 210MB

// ---------------- f32x2 helpers (packed fp32 FMA: 2x fp32 throughput) ----------
static __device__ __forceinline__ unsigned long long pk2(float lo, float hi) {
    unsigned long long r;
    asm("mov.b64 %0, {%1, %2};" : "=l"(r) : "f"(lo), "f"(hi));
    return r;
}
static __device__ __forceinline__ float2 upk2(unsigned long long v) {
    float2 f;
    asm("mov.b64 {%0, %1}, %2;" : "=f"(f.x), "=f"(f.y) : "l"(v));
    return f;
}
static __device__ __forceinline__ unsigned long long fma2(unsigned long long a,
                                                          unsigned long long b,
                                                          unsigned long long c) {
    unsigned long long d;
    asm("fma.rn.f32x2 %0, %1, %2, %3;" : "=l"(d) : "l"(a), "l"(b), "l"(c));
    return d;
}
static __device__ __forceinline__ float fast_sigmoid(float x) {
    return __fdividef(1.0f, 1.0f + __expf(-x));
}

// ---------------- K0: user profile -------------------------------------------
__global__ void user_kernel(const int* __restrict__ uid, const int* __restrict__ age,
                            const int* __restrict__ gender, const int* __restrict__ occup,
                            const float* __restrict__ ue, const float* __restrict__ at,
                            const float* __restrict__ gt, const float* __restrict__ ot) {
    int idx = blockIdx.x * blockDim.x + threadIdx.x;
    if (idx >= BB * DD) return;
    int b = idx >> 6, d = idx & 63;
    float v = ue[(size_t)uid[b] * DD + d] + gt[(size_t)gender[b] * DD + d] +
              at[(size_t)age[b] * DD + d] + ot[(size_t)occup[b] * DD + d];
    g_user_buf[idx] = 0.25f * v;
}

// ---------------- K1: adj[b,i,j] = sigmoid(sum_d it[i,d]*u[d]*it[j,d])*m_i*m_j --
// One CTA per b. item rows gathered+masked into transposed SMEM it_t[d][AS].
// 16x16 threads, per-thread 7 rows x 7 f32x2 column-pairs, two row passes.
__global__ __launch_bounds__(256) void adj_kernel(const int* __restrict__ mid_his,
                                                  const float* __restrict__ mask,
                                                  const float* __restrict__ mid_emb,
                                                  float* __restrict__ out_adj) {
    extern __shared__ float sm[];
    float* it_t = sm;              // [64][AS]
    float* u_sm = it_t + 64 * AS;  // [64]
    float* m_sm = u_sm + 64;       // [AS]

    int b = blockIdx.x;
    int t = threadIdx.x;

    if (t < 64) u_sm[t] = g_user_buf[b * 64 + t];
    for (int s = t; s < AS; s += 256) m_sm[s] = (s < SS) ? mask[b * SS + s] : 0.f;

    const float4* emb4 = (const float4*)mid_emb;
    for (int idx = t; idx < 16 * AS; idx += 256) {
        int d4 = idx / AS;
        int s = idx - d4 * AS;
        float4 v = make_float4(0.f, 0.f, 0.f, 0.f);
        if (s < SS) {
            int mid = mid_his[b * SS + s];
            float m = mask[b * SS + s];
            float4 e = emb4[(size_t)mid * 16 + d4];
            v.x = e.x * m; v.y = e.y * m; v.z = e.z * m; v.w = e.w * m;
        }
        it_t[(4 * d4 + 0) * AS + s] = v.x;
        it_t[(4 * d4 + 1) * AS + s] = v.y;
        it_t[(4 * d4 + 2) * AS + s] = v.z;
        it_t[(4 * d4 + 3) * AS + s] = v.w;
    }
    __syncthreads();

    int tx = t & 15, ty = t >> 4;
    int jb = tx * 14;

    for (int ipass = 0; ipass < 2; ipass++) {
        int ib = ipass * 112 + ty * 7;
        unsigned long long acc[7][7];
        #pragma unroll
        for (int ii = 0; ii < 7; ii++)
            #pragma unroll
            for (int jj = 0; jj < 7; jj++) acc[ii][jj] = 0ull;

        #pragma unroll 4
        for (int d = 0; d < 64; d++) {
            const float* row = it_t + d * AS;
            float ud = u_sm[d];
            unsigned long long av[7];
            #pragma unroll
            for (int ii = 0; ii < 7; ii++) {
                float a = row[ib + ii] * ud;
                av[ii] = pk2(a, a);
            }
            unsigned long long bv[7];
            #pragma unroll
            for (int jj = 0; jj < 7; jj++)
                bv[jj] = *(const unsigned long long*)(row + jb + 2 * jj);
            #pragma unroll
            for (int ii = 0; ii < 7; ii++)
                #pragma unroll
                for (int jj = 0; jj < 7; jj++)
                    acc[ii][jj] = fma2(av[ii], bv[jj], acc[ii][jj]);
        }

        #pragma unroll
        for (int ii = 0; ii < 7; ii++) {
            int i = ib + ii;
            if (i < SS) {
                float mi = m_sm[i];
                float* orow = out_adj + (size_t)b * (SS * SS) + (size_t)i * SS;
                #pragma unroll
                for (int jj = 0; jj < 7; jj++) {
                    int j = jb + 2 * jj;
                    if (j < SS) {
                        float2 x = upk2(acc[ii][jj]);
                        float2 o;
                        o.x = mi * m_sm[j] * fast_sigmoid(x.x);
                        o.y = mi * m_sm[j + 1] * fast_sigmoid(x.y);
                        *(float2*)(orow + j) = o;
                    }
                }
            }
        }
    }
}

// ---------------- K2: hat[b,e] per s: (128-row b-tile) x (E=256) x (K=64) ------
// Stores directly in routing layout g_hat[b][k][s][d].
__global__ __launch_bounds__(256) void hat_kernel(const int* __restrict__ mid_his,
                                                  const float* __restrict__ mask,
                                                  const float* __restrict__ mid_emb,
                                                  const float* __restrict__ w_capsule) {
    extern __shared__ float sm[];
    float* it_t = sm;            // [64][128]
    float* w_t = sm + 64 * 128;  // [64][256]

    int s = blockIdx.y;
    int b0 = blockIdx.x * 128;
    int t = threadIdx.x;

    const float4* emb4 = (const float4*)mid_emb;
    const float4* w4 = (const float4*)w_capsule;

    for (int idx = t; idx < 16 * 128; idx += 256) {
        int d4 = idx >> 7, bl = idx & 127;
        int gb = b0 + bl;
        int mid = mid_his[gb * SS + s];
        float m = mask[gb * SS + s];
        float4 e = emb4[(size_t)mid * 16 + d4];
        it_t[(4 * d4 + 0) * 128 + bl] = e.x * m;
        it_t[(4 * d4 + 1) * 128 + bl] = e.y * m;
        it_t[(4 * d4 + 2) * 128 + bl] = e.z * m;
        it_t[(4 * d4 + 3) * 128 + bl] = e.w * m;
    }
    for (int idx = t; idx < 16 * 256; idx += 256) {
        int d4 = idx >> 8, e = idx & 255;
        float4 v = w4[((size_t)s * 256 + e) * 16 + d4];
        w_t[(4 * d4 + 0) * 256 + e] = v.x;
        w_t[(4 * d4 + 1) * 256 + e] = v.y;
        w_t[(4 * d4 + 2) * 256 + e] = v.z;
        w_t[(4 * d4 + 3) * 256 + e] = v.w;
    }
    __syncthreads();

    int tx = t & 15, ty = t >> 4;
    unsigned long long acc[8][8];
    #pragma unroll
    for (int ii = 0; ii < 8; ii++)
        #pragma unroll
        for (int jj = 0; jj < 8; jj++) acc[ii][jj] = 0ull;

    #pragma unroll 2
    for (int d = 0; d < 64; d++) {
        const float* ir = it_t + d * 128;
        const float* wr = w_t + d * 256;
        unsigned long long av[8];
        #pragma unroll
        for (int ii = 0; ii < 8; ii++) {
            float a = ir[ty + 16 * ii];
            av[ii] = pk2(a, a);
        }
        unsigned long long bv[8];
        #pragma unroll
        for (int jj = 0; jj < 8; jj++)
            bv[jj] = *(const unsigned long long*)(wr + 2 * tx + 32 * jj);
        #pragma unroll
        for (int ii = 0; ii < 8; ii++)
            #pragma unroll
            for (int jj = 0; jj < 8; jj++)
                acc[ii][jj] = fma2(av[ii], bv[jj], acc[ii][jj]);
    }

    #pragma unroll
    for (int ii = 0; ii < 8; ii++) {
        int gb = b0 + ty + 16 * ii;
        #pragma unroll
        for (int jj = 0; jj < 8; jj++) {
            int e = 2 * tx + 32 * jj;
            int k = e >> 6;
            int dd = e & 63;
            float2 v = upk2(acc[ii][jj]);
            *(float2*)(g_hat_buf + (((size_t)gb * NI + k) * SS + s) * DD + dd) = v;
        }
    }
}

// ---------------- K3: dynamic routing, one CTA per b, hat[b] in SMEM -----------
__global__ __launch_bounds__(512) void route_kernel(const float* __restrict__ mask,
                                                    float* __restrict__ out_cap) {
    extern __shared__ float sm[];
    float* hat_s = sm;                    // NI*SS*DD = 51200
    float* cw    = hat_s + NI * SS * DD;  // 800
    float* swm   = cw + NI * SS;          // 800
    float* cap2  = swm + NI * SS;         // 512
    float* capsm = cap2 + 512;            // 256
    float* msk   = capsm + 256;           // 200
    float* nrm   = msk + 200;             // 4

    int b = blockIdx.x;
    int t = threadIdx.x;
    int lane = t & 31, w = t >> 5;

    const float4* src = (const float4*)(g_hat_buf + (size_t)b * NI * SS * DD);
    float4* dst = (float4*)hat_s;
    for (int i = t; i < NI * SS * DD / 4; i += 512) dst[i] = src[i];
    for (int i = t; i < NI * SS; i += 512) cw[i] = 0.f;
    if (t < SS) msk[t] = mask[b * SS + t];
    __syncthreads();

    for (int it = 0; it < 3; it++) {
        // softmax over k (4 values) per s, masked
        if (t < SS) {
            float c0 = cw[0 * SS + t], c1 = cw[1 * SS + t];
            float c2 = cw[2 * SS + t], c3 = cw[3 * SS + t];
            float mx = fmaxf(fmaxf(c0, c1), fmaxf(c2, c3));
            float e0 = expf(c0 - mx), e1 = expf(c1 - mx);
            float e2 = expf(c2 - mx), e3 = expf(c3 - mx);
            float inv = 1.0f / (e0 + e1 + e2 + e3);
            float z = (msk[t] != 0.f) ? inv : 0.f;
            swm[0 * SS + t] = e0 * z;
            swm[1 * SS + t] = e1 * z;
            swm[2 * SS + t] = e2 * z;
            swm[3 * SS + t] = e3 * z;
        }
        __syncthreads();

        // cap[k][d] = sum_s sw[k][s]*hat[k][s][d]  (split s into halves)
        {
            int h = t >> 8;  // 0..1
            int r = t & 255;
            int k = r >> 6, d = r & 63;
            const float* hp = hat_s + (k * SS + h * 100) * DD + d;
            const float* sp = swm + k * SS + h * 100;
            float acc = 0.f;
            #pragma unroll 4
            for (int s2 = 0; s2 < 100; s2++) acc = fmaf(sp[s2], hp[s2 * DD], acc);
            cap2[t] = acc;
        }
        __syncthreads();
        if (t < 256) capsm[t] = cap2[t] + cap2[256 + t];
        __syncthreads();
        if (t < NI) {
            float n = 0.f;
            for (int d = 0; d < DD; d++) {
                float v = capsm[t * DD + d];
                n = fmaf(v, v, n);
            }
            nrm[t] = n;
        }
        __syncthreads();
        if (t < 256) {
            int k = t >> 6;
            float n = nrm[k];
            float f = n / ((1.0f + n) * sqrtf(n + 1e-9f));  // squash factor
            capsm[t] = capsm[t] * f;
        }
        __syncthreads();

        if (it < 2) {
            // cw[k][s] += dot_d(hat[k][s][:], cap[k][:]); one warp per (k, s mod 4)
            int k = w >> 2;
            int s0 = w & 3;
            float c0 = capsm[k * DD + lane];
            float c1 = capsm[k * DD + 32 + lane];
            for (int s2 = s0; s2 < SS; s2 += 4) {
                const float* hrow = hat_s + (k * SS + s2) * DD;
                float v = hrow[lane] * c0 + hrow[32 + lane] * c1;
                #pragma unroll
                for (int off = 16; off > 0; off >>= 1)
                    v += __shfl_xor_sync(0xffffffffu, v, off);
                if (lane == 0) cw[k * SS + s2] += v;
            }
            __syncthreads();
        } else {
            if (t < 256) out_cap[(size_t)b * 256 + t] = capsm[t];
        }
    }
}

// ---------------- launch -------------------------------------------------------
extern "C" void kernel_launch(void* const* d_in, const int* in_sizes, int n_in,
                              void* d_out, int out_size) {
    const int* uid = (const int*)d_in[0];
    const int* age = (const int*)d_in[1];
    const int* gender = (const int*)d_in[2];
    const int* occup = (const int*)d_in[3];
    const int* mid_his = (const int*)d_in[4];
    const float* mask = (const float*)d_in[5];
    const float* user_emb = (const float*)d_in[6];
    const float* age_tab = (const float*)d_in[7];
    const float* gender_tab = (const float*)d_in[8];
    const float* occup_tab = (const float*)d_in[9];
    const float* mid_emb = (const float*)d_in[10];
    const float* w_capsule = (const float*)d_in[11];

    float* out = (float*)d_out;
    float* out_cap = out;                       // [B, NI, D]
    float* out_adj = out + (size_t)BB * NI * DD;  // [B, S, S]

    const int ADJ_SMEM = (64 * AS + 64 + AS) * 4;                 // 58496 B
    const int HAT_SMEM = (64 * 128 + 64 * 256) * 4;               // 98304 B
    const int ROUTE_SMEM = (NI * SS * DD + 2 * NI * SS + 512 + 256 + 200 + 4) * 4;  // 215088 B

    cudaFuncSetAttribute(adj_kernel, cudaFuncAttributeMaxDynamicSharedMemorySize, ADJ_SMEM);
    cudaFuncSetAttribute(hat_kernel, cudaFuncAttributeMaxDynamicSharedMemorySize, HAT_SMEM);
    cudaFuncSetAttribute(route_kernel, cudaFuncAttributeMaxDynamicSharedMemorySize, ROUTE_SMEM);

    user_kernel<<<(BB * DD + 255) / 256, 256>>>(uid, age, gender, occup, user_emb,
                                                age_tab, gender_tab, occup_tab);
    adj_kernel<<<BB, 256, ADJ_SMEM>>>(mid_his, mask, mid_emb, out_adj);
    hat_kernel<<<dim3(8, 200), 256, HAT_SMEM>>>(mid_his, mask, mid_emb, w_capsule);
    route_kernel<<<BB, 512, ROUTE_SMEM>>>(mask, out_cap);
}

// round 6
// speedup vs baseline: 1.0387x; 1.0387x over previous
#include <cuda_runtime.h>
#include <math.h>

#define BB 1024
#define SS 200
#define DD 64
#define NI 4
#define AS 224   // padded S for adj tiling

// ---------------- scratch (__device__ globals: allocation-free) ----------------
__device__ float g_hat_buf[(size_t)BB * NI * SS * DD];   // [b][k][s][d], 210MB

// ---------------- f32x2 helpers (packed fp32 FMA: 2x fp32 throughput) ----------
static __device__ __forceinline__ unsigned long long pk2(float lo, float hi) {
    unsigned long long r;
    asm("mov.b64 %0, {%1, %2};" : "=l"(r) : "f"(lo), "f"(hi));
    return r;
}
static __device__ __forceinline__ float2 upk2(unsigned long long v) {
    float2 f;
    asm("mov.b64 {%0, %1}, %2;" : "=f"(f.x), "=f"(f.y) : "l"(v));
    return f;
}
static __device__ __forceinline__ unsigned long long fma2(unsigned long long a,
                                                          unsigned long long b,
                                                          unsigned long long c) {
    unsigned long long d;
    asm("fma.rn.f32x2 %0, %1, %2, %3;" : "=l"(d) : "l"(a), "l"(b), "l"(c));
    return d;
}
static __device__ __forceinline__ float fast_sigmoid(float x) {
    return __fdividef(1.0f, 1.0f + __expf(-x));
}

// ---------------- K1: adj[b,i,j] = sigmoid(sum_d it[i,d]*u[d]*it[j,d])*m_i*m_j --
// One CTA per b. user profile gathered inline (user_kernel fused away).
// 16x16 threads, per-thread 7 rows x 7 f32x2 column-pairs, two row passes.
__global__ __launch_bounds__(256) void adj_kernel(const int* __restrict__ uid,
                                                  const int* __restrict__ age,
                                                  const int* __restrict__ gender,
                                                  const int* __restrict__ occup,
                                                  const float* __restrict__ ue,
                                                  const float* __restrict__ at,
                                                  const float* __restrict__ gt,
                                                  const float* __restrict__ ot,
                                                  const int* __restrict__ mid_his,
                                                  const float* __restrict__ mask,
                                                  const float* __restrict__ mid_emb,
                                                  float* __restrict__ out_adj) {
    extern __shared__ float sm[];
    float* it_t = sm;              // [64][AS]
    float* u_sm = it_t + 64 * AS;  // [64]
    float* m_sm = u_sm + 64;       // [AS]

    int b = blockIdx.x;
    int t = threadIdx.x;

    if (t < 64) {
        float v = ue[(size_t)uid[b] * DD + t] + gt[(size_t)gender[b] * DD + t] +
                  at[(size_t)age[b] * DD + t] + ot[(size_t)occup[b] * DD + t];
        u_sm[t] = 0.25f * v;
    }
    for (int s = t; s < AS; s += 256) m_sm[s] = (s < SS) ? mask[b * SS + s] : 0.f;

    const float4* emb4 = (const float4*)mid_emb;
    for (int idx = t; idx < 16 * AS; idx += 256) {
        int d4 = idx / AS;
        int s = idx - d4 * AS;
        float4 v = make_float4(0.f, 0.f, 0.f, 0.f);
        if (s < SS) {
            int mid = mid_his[b * SS + s];
            float m = mask[b * SS + s];
            float4 e = emb4[(size_t)mid * 16 + d4];
            v.x = e.x * m; v.y = e.y * m; v.z = e.z * m; v.w = e.w * m;
        }
        it_t[(4 * d4 + 0) * AS + s] = v.x;
        it_t[(4 * d4 + 1) * AS + s] = v.y;
        it_t[(4 * d4 + 2) * AS + s] = v.z;
        it_t[(4 * d4 + 3) * AS + s] = v.w;
    }
    __syncthreads();

    int tx = t & 15, ty = t >> 4;
    int jb = tx * 14;

    for (int ipass = 0; ipass < 2; ipass++) {
        int ib = ipass * 112 + ty * 7;
        unsigned long long acc[7][7];
        #pragma unroll
        for (int ii = 0; ii < 7; ii++)
            #pragma unroll
            for (int jj = 0; jj < 7; jj++) acc[ii][jj] = 0ull;

        #pragma unroll 4
        for (int d = 0; d < 64; d++) {
            const float* row = it_t + d * AS;
            float ud = u_sm[d];
            unsigned long long av[7];
            #pragma unroll
            for (int ii = 0; ii < 7; ii++) {
                float a = row[ib + ii] * ud;
                av[ii] = pk2(a, a);
            }
            unsigned long long bv[7];
            #pragma unroll
            for (int jj = 0; jj < 7; jj++)
                bv[jj] = *(const unsigned long long*)(row + jb + 2 * jj);
            #pragma unroll
            for (int ii = 0; ii < 7; ii++)
                #pragma unroll
                for (int jj = 0; jj < 7; jj++)
                    acc[ii][jj] = fma2(av[ii], bv[jj], acc[ii][jj]);
        }

        #pragma unroll
        for (int ii = 0; ii < 7; ii++) {
            int i = ib + ii;
            if (i < SS) {
                float mi = m_sm[i];
                float* orow = out_adj + (size_t)b * (SS * SS) + (size_t)i * SS;
                #pragma unroll
                for (int jj = 0; jj < 7; jj++) {
                    int j = jb + 2 * jj;
                    if (j < SS) {
                        float2 x = upk2(acc[ii][jj]);
                        float2 o;
                        o.x = mi * m_sm[j] * fast_sigmoid(x.x);
                        o.y = mi * m_sm[j + 1] * fast_sigmoid(x.y);
                        *(float2*)(orow + j) = o;
                    }
                }
            }
        }
    }
}

// ---------------- K2: hat, 512 threads (16 warps), tile 8 rows x 4 pairs -------
// Stores directly in routing layout g_hat[b][k][s][d].
__global__ __launch_bounds__(512) void hat_kernel(const int* __restrict__ mid_his,
                                                  const float* __restrict__ mask,
                                                  const float* __restrict__ mid_emb,
                                                  const float* __restrict__ w_capsule) {
    extern __shared__ float sm[];
    float* it_t = sm;            // [64][128]
    float* w_t = sm + 64 * 128;  // [64][256]

    int s = blockIdx.y;
    int b0 = blockIdx.x * 128;
    int t = threadIdx.x;

    const float4* emb4 = (const float4*)mid_emb;
    const float4* w4 = (const float4*)w_capsule;

    for (int idx = t; idx < 16 * 128; idx += 512) {
        int d4 = idx >> 7, bl = idx & 127;
        int gb = b0 + bl;
        int mid = mid_his[gb * SS + s];
        float m = mask[gb * SS + s];
        float4 e = emb4[(size_t)mid * 16 + d4];
        it_t[(4 * d4 + 0) * 128 + bl] = e.x * m;
        it_t[(4 * d4 + 1) * 128 + bl] = e.y * m;
        it_t[(4 * d4 + 2) * 128 + bl] = e.z * m;
        it_t[(4 * d4 + 3) * 128 + bl] = e.w * m;
    }
    for (int idx = t; idx < 16 * 256; idx += 512) {
        int d4 = idx >> 8, e = idx & 255;
        float4 v = w4[((size_t)s * 256 + e) * 16 + d4];
        w_t[(4 * d4 + 0) * 256 + e] = v.x;
        w_t[(4 * d4 + 1) * 256 + e] = v.y;
        w_t[(4 * d4 + 2) * 256 + e] = v.z;
        w_t[(4 * d4 + 3) * 256 + e] = v.w;
    }
    __syncthreads();

    int tx = t & 31, ty = t >> 5;  // tx: e-pairs, ty: b-rows; warp = one ty
    unsigned long long acc[8][4];
    #pragma unroll
    for (int ii = 0; ii < 8; ii++)
        #pragma unroll
        for (int jj = 0; jj < 4; jj++) acc[ii][jj] = 0ull;

    #pragma unroll 2
    for (int d = 0; d < 64; d++) {
        const float* ir = it_t + d * 128;
        const float* wr = w_t + d * 256;
        unsigned long long av[8];
        #pragma unroll
        for (int ii = 0; ii < 8; ii++) {
            float a = ir[ty + 16 * ii];
            av[ii] = pk2(a, a);
        }
        unsigned long long bv[4];
        #pragma unroll
        for (int jj = 0; jj < 4; jj++)
            bv[jj] = *(const unsigned long long*)(wr + 2 * tx + 64 * jj);
        #pragma unroll
        for (int ii = 0; ii < 8; ii++)
            #pragma unroll
            for (int jj = 0; jj < 4; jj++)
                acc[ii][jj] = fma2(av[ii], bv[jj], acc[ii][jj]);
    }

    // e = 2*tx + 64*jj  ->  k = jj, dd = 2*tx
    #pragma unroll
    for (int ii = 0; ii < 8; ii++) {
        int gb = b0 + ty + 16 * ii;
        #pragma unroll
        for (int jj = 0; jj < 4; jj++) {
            float2 v = upk2(acc[ii][jj]);
            *(float2*)(g_hat_buf + (((size_t)gb * NI + jj) * SS + s) * DD + 2 * tx) = v;
        }
    }
}

// ---------------- K3: routing v2 — 1024 threads, wide phases, shuffle reduces ---
#define RT 1024
__global__ __launch_bounds__(RT) void route_kernel(const float* __restrict__ mask,
                                                   float* __restrict__ out_cap) {
    extern __shared__ float sm[];
    float* hat_s    = sm;                  // 51200
    float* cw       = hat_s + NI * SS * DD;  // 800
    float* swm      = cw + NI * SS;          // 800
    float* cap_part = swm + NI * SS;         // 1024
    float* capsm    = cap_part + 1024;       // 256
    float* nrm_part = capsm + 256;           // 8
    float* msk      = nrm_part + 8;          // 200

    int b = blockIdx.x;
    int t = threadIdx.x;
    int lane = t & 31, w = t >> 5;

    // load hat[b] (200KB) with all 32 warps
    const float4* src = (const float4*)(g_hat_buf + (size_t)b * NI * SS * DD);
    float4* dst = (float4*)hat_s;
    for (int i = t; i < NI * SS * DD / 4; i += RT) dst[i] = src[i];
    if (t < NI * SS) cw[t] = 0.f;
    if (t >= 800 && t < 800 + SS) msk[t - 800] = mask[b * SS + (t - 800)];
    __syncthreads();

    for (int it = 0; it < 3; it++) {
        // masked softmax over k (4 values) per s
        if (t < SS) {
            float c0 = cw[0 * SS + t], c1 = cw[1 * SS + t];
            float c2 = cw[2 * SS + t], c3 = cw[3 * SS + t];
            float mx = fmaxf(fmaxf(c0, c1), fmaxf(c2, c3));
            float e0 = __expf(c0 - mx), e1 = __expf(c1 - mx);
            float e2 = __expf(c2 - mx), e3 = __expf(c3 - mx);
            float inv = __fdividef(1.0f, e0 + e1 + e2 + e3);
            float z = (msk[t] != 0.f) ? inv : 0.f;
            swm[0 * SS + t] = e0 * z;
            swm[1 * SS + t] = e1 * z;
            swm[2 * SS + t] = e2 * z;
            swm[3 * SS + t] = e3 * z;
        }
        __syncthreads();

        // cap[k][d] = sum_s sw[k][s]*hat[k][s][d], s split 4 ways (all 1024 thr)
        {
            int part = t >> 8;       // 0..3
            int r = t & 255;
            int k = r >> 6, d = r & 63;
            const float* hp = hat_s + (k * SS + part * 50) * DD + d;
            const float* sp = swm + k * SS + part * 50;
            float acc = 0.f;
            #pragma unroll 5
            for (int s2 = 0; s2 < 50; s2++) acc = fmaf(sp[s2], hp[s2 * DD], acc);
            cap_part[part * 256 + r] = acc;
        }
        __syncthreads();

        // combine partials + squared-norm via warp shuffles (warps 0..7)
        float cval = 0.f;
        if (t < 256) {
            cval = cap_part[t] + cap_part[256 + t] + cap_part[512 + t] + cap_part[768 + t];
            float v = cval * cval;
            #pragma unroll
            for (int off = 16; off > 0; off >>= 1)
                v += __shfl_xor_sync(0xffffffffu, v, off);
            if (lane == 0) nrm_part[w] = v;  // w in 0..7, 2 warps per k
        }
        __syncthreads();
        if (t < 256) {
            int k = t >> 6;
            float n = nrm_part[2 * k] + nrm_part[2 * k + 1];
            float f = n / ((1.0f + n) * sqrtf(n + 1e-9f));  // squash factor
            capsm[t] = cval * f;
        }
        __syncthreads();

        if (it < 2) {
            // cw[k][s] += dot_d(hat[k][s][:], cap[k][:]); 8 warps per k
            int k = w >> 3;
            int s0 = w & 7;
            float c0 = capsm[k * DD + lane];
            float c1 = capsm[k * DD + 32 + lane];
            for (int s2 = s0; s2 < SS; s2 += 8) {
                const float* hrow = hat_s + (k * SS + s2) * DD;
                float v = hrow[lane] * c0 + hrow[32 + lane] * c1;
                #pragma unroll
                for (int off = 16; off > 0; off >>= 1)
                    v += __shfl_xor_sync(0xffffffffu, v, off);
                if (lane == 0) cw[k * SS + s2] += v;
            }
            __syncthreads();
        } else {
            if (t < 256) out_cap[(size_t)b * 256 + t] = capsm[t];
        }
    }
}

// ---------------- launch -------------------------------------------------------
extern "C" void kernel_launch(void* const* d_in, const int* in_sizes, int n_in,
                              void* d_out, int out_size) {
    const int* uid = (const int*)d_in[0];
    const int* age = (const int*)d_in[1];
    const int* gender = (const int*)d_in[2];
    const int* occup = (const int*)d_in[3];
    const int* mid_his = (const int*)d_in[4];
    const float* mask = (const float*)d_in[5];
    const float* user_emb = (const float*)d_in[6];
    const float* age_tab = (const float*)d_in[7];
    const float* gender_tab = (const float*)d_in[8];
    const float* occup_tab = (const float*)d_in[9];
    const float* mid_emb = (const float*)d_in[10];
    const float* w_capsule = (const float*)d_in[11];

    float* out = (float*)d_out;
    float* out_cap = out;                         // [B, NI, D]
    float* out_adj = out + (size_t)BB * NI * DD;  // [B, S, S]

    const int ADJ_SMEM = (64 * AS + 64 + AS) * 4;    // 58496 B
    const int HAT_SMEM = (64 * 128 + 64 * 256) * 4;  // 98304 B
    const int ROUTE_SMEM = (NI * SS * DD + 2 * NI * SS + 1024 + 256 + 8 + 200) * 4;  // 217152 B

    cudaFuncSetAttribute(adj_kernel, cudaFuncAttributeMaxDynamicSharedMemorySize, ADJ_SMEM);
    cudaFuncSetAttribute(hat_kernel, cudaFuncAttributeMaxDynamicSharedMemorySize, HAT_SMEM);
    cudaFuncSetAttribute(route_kernel, cudaFuncAttributeMaxDynamicSharedMemorySize, ROUTE_SMEM);

    adj_kernel<<<BB, 256, ADJ_SMEM>>>(uid, age, gender, occup, user_emb, age_tab,
                                      gender_tab, occup_tab, mid_his, mask, mid_emb,
                                      out_adj);
    hat_kernel<<<dim3(8, 200), 512, HAT_SMEM>>>(mid_his, mask, mid_emb, w_capsule);
    route_kernel<<<BB, RT, ROUTE_SMEM>>>(mask, out_cap);
}

// round 7
// speedup vs baseline: 1.0581x; 1.0187x over previous
#include <cuda_runtime.h>
#include <math.h>

#define BB 1024
#define SS 200
#define DD 64
#define NI 4
#define AS 224   // padded S for adj tiling

// ---------------- scratch (__device__ globals: allocation-free) ----------------
__device__ float g_hat_buf[(size_t)BB * NI * SS * DD];   // [b][k][s][d], 210MB

// ---------------- f32x2 helpers (packed fp32 FMA: 2x fp32 throughput) ----------
static __device__ __forceinline__ unsigned long long pk2(float lo, float hi) {
    unsigned long long r;
    asm("mov.b64 %0, {%1, %2};" : "=l"(r) : "f"(lo), "f"(hi));
    return r;
}
static __device__ __forceinline__ float2 upk2(unsigned long long v) {
    float2 f;
    asm("mov.b64 {%0, %1}, %2;" : "=f"(f.x), "=f"(f.y) : "l"(v));
    return f;
}
static __device__ __forceinline__ unsigned long long fma2(unsigned long long a,
                                                          unsigned long long b,
                                                          unsigned long long c) {
    unsigned long long d;
    asm("fma.rn.f32x2 %0, %1, %2, %3;" : "=l"(d) : "l"(a), "l"(b), "l"(c));
    return d;
}
static __device__ __forceinline__ float fast_sigmoid(float x) {
    return __fdividef(1.0f, 1.0f + __expf(-x));
}

// ---------------- K1: adj, SYMMETRIC: compute only tiles touching i<=j ---------
// 288 threads; slot t in [0,272) -> tile (I,J): J from triangular inversion,
// I = slot - J(J+1), tile rows [7I,7I+7) x cols [14J,14J+14).
// Coverage: all cells i<=j computed (I <= 2J+1). Writes: normal iff i<=j,
// transposed iff i<j  ->  each output cell written exactly once.
#define ADJ_T 288
__global__ __launch_bounds__(ADJ_T) void adj_kernel(const int* __restrict__ uid,
                                                    const int* __restrict__ age,
                                                    const int* __restrict__ gender,
                                                    const int* __restrict__ occup,
                                                    const float* __restrict__ ue,
                                                    const float* __restrict__ at,
                                                    const float* __restrict__ gt,
                                                    const float* __restrict__ ot,
                                                    const int* __restrict__ mid_his,
                                                    const float* __restrict__ mask,
                                                    const float* __restrict__ mid_emb,
                                                    float* __restrict__ out_adj) {
    extern __shared__ float sm[];
    float* it_t = sm;               // [64][AS]  item_his (masked)
    float* hu_t = it_t + 64 * AS;   // [64][AS]  item_his * u[d]
    float* u_sm = hu_t + 64 * AS;   // [64]
    float* m_sm = u_sm + 64;        // [AS]

    int b = blockIdx.x;
    int t = threadIdx.x;

    if (t < 64) {
        float v = ue[(size_t)uid[b] * DD + t] + gt[(size_t)gender[b] * DD + t] +
                  at[(size_t)age[b] * DD + t] + ot[(size_t)occup[b] * DD + t];
        u_sm[t] = 0.25f * v;
    }
    for (int s = t; s < AS; s += ADJ_T) m_sm[s] = (s < SS) ? mask[b * SS + s] : 0.f;
    __syncthreads();   // u_sm ready before hu_t writes

    const float4* emb4 = (const float4*)mid_emb;
    for (int idx = t; idx < 16 * AS; idx += ADJ_T) {
        int d4 = idx / AS;
        int s = idx - d4 * AS;
        float4 v = make_float4(0.f, 0.f, 0.f, 0.f);
        if (s < SS) {
            int mid = mid_his[b * SS + s];
            float m = mask[b * SS + s];
            float4 e = emb4[(size_t)mid * 16 + d4];
            v.x = e.x * m; v.y = e.y * m; v.z = e.z * m; v.w = e.w * m;
        }
        int d0 = 4 * d4;
        it_t[(d0 + 0) * AS + s] = v.x;
        it_t[(d0 + 1) * AS + s] = v.y;
        it_t[(d0 + 2) * AS + s] = v.z;
        it_t[(d0 + 3) * AS + s] = v.w;
        hu_t[(d0 + 0) * AS + s] = v.x * u_sm[d0 + 0];
        hu_t[(d0 + 1) * AS + s] = v.y * u_sm[d0 + 1];
        hu_t[(d0 + 2) * AS + s] = v.z * u_sm[d0 + 2];
        hu_t[(d0 + 3) * AS + s] = v.w * u_sm[d0 + 3];
    }
    __syncthreads();

    if (t < 272) {
        // triangular inversion: J(J+1) <= t < (J+1)(J+2)
        int J = (int)((sqrtf((float)(4 * t + 1)) - 1.0f) * 0.5f);
        while ((J + 1) * (J + 2) <= t) ++J;
        while (J * (J + 1) > t) --J;
        int I = t - J * (J + 1);
        int ib = 7 * I;
        int jb = 14 * J;

        unsigned long long acc[7][7];
        #pragma unroll
        for (int ii = 0; ii < 7; ii++)
            #pragma unroll
            for (int jj = 0; jj < 7; jj++) acc[ii][jj] = 0ull;

        #pragma unroll 4
        for (int d = 0; d < 64; d++) {
            const float* hrow = hu_t + d * AS;
            const float* irow = it_t + d * AS;
            unsigned long long av[7];
            #pragma unroll
            for (int ii = 0; ii < 7; ii++) {
                float a = hrow[ib + ii];
                av[ii] = pk2(a, a);
            }
            unsigned long long bv[7];
            #pragma unroll
            for (int jj = 0; jj < 7; jj++)
                bv[jj] = *(const unsigned long long*)(irow + jb + 2 * jj);
            #pragma unroll
            for (int ii = 0; ii < 7; ii++)
                #pragma unroll
                for (int jj = 0; jj < 7; jj++)
                    acc[ii][jj] = fma2(av[ii], bv[jj], acc[ii][jj]);
        }

        float* ob = out_adj + (size_t)b * (SS * SS);
        #pragma unroll
        for (int ii = 0; ii < 7; ii++) {
            int i = ib + ii;
            if (i < SS) {
                float mi = m_sm[i];
                #pragma unroll
                for (int jj = 0; jj < 7; jj++) {
                    int j = jb + 2 * jj;
                    if (j < SS) {   // j+1 < SS too (j even, SS even)
                        float2 x = upk2(acc[ii][jj]);
                        float xv = mi * m_sm[j] * fast_sigmoid(x.x);
                        float yv = mi * m_sm[j + 1] * fast_sigmoid(x.y);
                        // normal writes (cells (i,j),(i,j+1)): iff i <= col
                        if (i <= j) {
                            float2 o; o.x = xv; o.y = yv;
                            *(float2*)(ob + (size_t)i * SS + j) = o;
                        } else if (i == j + 1) {
                            ob[(size_t)i * SS + j + 1] = yv;   // diagonal cell
                        }
                        // transposed writes (cells (j,i),(j+1,i)): iff i < col
                        if (i < j) {
                            ob[(size_t)j * SS + i] = xv;
                            ob[(size_t)(j + 1) * SS + i] = yv;
                        } else if (i == j) {
                            ob[(size_t)(j + 1) * SS + i] = yv;
                        }
                    }
                }
            }
        }
    }
}

// ---------------- K2: hat, 512 threads (16 warps), tile 8 rows x 4 pairs -------
// Stores directly in routing layout g_hat[b][k][s][d].
__global__ __launch_bounds__(512) void hat_kernel(const int* __restrict__ mid_his,
                                                  const float* __restrict__ mask,
                                                  const float* __restrict__ mid_emb,
                                                  const float* __restrict__ w_capsule) {
    extern __shared__ float sm[];
    float* it_t = sm;            // [64][128]
    float* w_t = sm + 64 * 128;  // [64][256]

    int s = blockIdx.y;
    int b0 = blockIdx.x * 128;
    int t = threadIdx.x;

    const float4* emb4 = (const float4*)mid_emb;
    const float4* w4 = (const float4*)w_capsule;

    for (int idx = t; idx < 16 * 128; idx += 512) {
        int d4 = idx >> 7, bl = idx & 127;
        int gb = b0 + bl;
        int mid = mid_his[gb * SS + s];
        float m = mask[gb * SS + s];
        float4 e = emb4[(size_t)mid * 16 + d4];
        it_t[(4 * d4 + 0) * 128 + bl] = e.x * m;
        it_t[(4 * d4 + 1) * 128 + bl] = e.y * m;
        it_t[(4 * d4 + 2) * 128 + bl] = e.z * m;
        it_t[(4 * d4 + 3) * 128 + bl] = e.w * m;
    }
    for (int idx = t; idx < 16 * 256; idx += 512) {
        int d4 = idx >> 8, e = idx & 255;
        float4 v = w4[((size_t)s * 256 + e) * 16 + d4];
        w_t[(4 * d4 + 0) * 256 + e] = v.x;
        w_t[(4 * d4 + 1) * 256 + e] = v.y;
        w_t[(4 * d4 + 2) * 256 + e] = v.z;
        w_t[(4 * d4 + 3) * 256 + e] = v.w;
    }
    __syncthreads();

    int tx = t & 31, ty = t >> 5;  // tx: e-pairs, ty: b-rows; warp = one ty
    unsigned long long acc[8][4];
    #pragma unroll
    for (int ii = 0; ii < 8; ii++)
        #pragma unroll
        for (int jj = 0; jj < 4; jj++) acc[ii][jj] = 0ull;

    #pragma unroll 2
    for (int d = 0; d < 64; d++) {
        const float* ir = it_t + d * 128;
        const float* wr = w_t + d * 256;
        unsigned long long av[8];
        #pragma unroll
        for (int ii = 0; ii < 8; ii++) {
            float a = ir[ty + 16 * ii];
            av[ii] = pk2(a, a);
        }
        unsigned long long bv[4];
        #pragma unroll
        for (int jj = 0; jj < 4; jj++)
            bv[jj] = *(const unsigned long long*)(wr + 2 * tx + 64 * jj);
        #pragma unroll
        for (int ii = 0; ii < 8; ii++)
            #pragma unroll
            for (int jj = 0; jj < 4; jj++)
                acc[ii][jj] = fma2(av[ii], bv[jj], acc[ii][jj]);
    }

    // e = 2*tx + 64*jj  ->  k = jj, dd = 2*tx
    #pragma unroll
    for (int ii = 0; ii < 8; ii++) {
        int gb = b0 + ty + 16 * ii;
        #pragma unroll
        for (int jj = 0; jj < 4; jj++) {
            float2 v = upk2(acc[ii][jj]);
            *(float2*)(g_hat_buf + (((size_t)gb * NI + jj) * SS + s) * DD + 2 * tx) = v;
        }
    }
}

// ---------------- K3: routing v2 — 1024 threads, wide phases, shuffle reduces ---
#define RT 1024
__global__ __launch_bounds__(RT) void route_kernel(const float* __restrict__ mask,
                                                   float* __restrict__ out_cap) {
    extern __shared__ float sm[];
    float* hat_s    = sm;                  // 51200
    float* cw       = hat_s + NI * SS * DD;  // 800
    float* swm      = cw + NI * SS;          // 800
    float* cap_part = swm + NI * SS;         // 1024
    float* capsm    = cap_part + 1024;       // 256
    float* nrm_part = capsm + 256;           // 8
    float* msk      = nrm_part + 8;          // 200

    int b = blockIdx.x;
    int t = threadIdx.x;
    int lane = t & 31, w = t >> 5;

    // load hat[b] (200KB) with all 32 warps
    const float4* src = (const float4*)(g_hat_buf + (size_t)b * NI * SS * DD);
    float4* dst = (float4*)hat_s;
    for (int i = t; i < NI * SS * DD / 4; i += RT) dst[i] = src[i];
    if (t < NI * SS) cw[t] = 0.f;
    if (t >= 800 && t < 800 + SS) msk[t - 800] = mask[b * SS + (t - 800)];
    __syncthreads();

    for (int it = 0; it < 3; it++) {
        // masked softmax over k (4 values) per s
        if (t < SS) {
            float c0 = cw[0 * SS + t], c1 = cw[1 * SS + t];
            float c2 = cw[2 * SS + t], c3 = cw[3 * SS + t];
            float mx = fmaxf(fmaxf(c0, c1), fmaxf(c2, c3));
            float e0 = __expf(c0 - mx), e1 = __expf(c1 - mx);
            float e2 = __expf(c2 - mx), e3 = __expf(c3 - mx);
            float inv = __fdividef(1.0f, e0 + e1 + e2 + e3);
            float z = (msk[t] != 0.f) ? inv : 0.f;
            swm[0 * SS + t] = e0 * z;
            swm[1 * SS + t] = e1 * z;
            swm[2 * SS + t] = e2 * z;
            swm[3 * SS + t] = e3 * z;
        }
        __syncthreads();

        // cap[k][d] = sum_s sw[k][s]*hat[k][s][d], s split 4 ways (all 1024 thr)
        {
            int part = t >> 8;       // 0..3
            int r = t & 255;
            int k = r >> 6, d = r & 63;
            const float* hp = hat_s + (k * SS + part * 50) * DD + d;
            const float* sp = swm + k * SS + part * 50;
            float acc = 0.f;
            #pragma unroll 5
            for (int s2 = 0; s2 < 50; s2++) acc = fmaf(sp[s2], hp[s2 * DD], acc);
            cap_part[part * 256 + r] = acc;
        }
        __syncthreads();

        // combine partials + squared-norm via warp shuffles (warps 0..7)
        float cval = 0.f;
        if (t < 256) {
            cval = cap_part[t] + cap_part[256 + t] + cap_part[512 + t] + cap_part[768 + t];
            float v = cval * cval;
            #pragma unroll
            for (int off = 16; off > 0; off >>= 1)
                v += __shfl_xor_sync(0xffffffffu, v, off);
            if (lane == 0) nrm_part[w] = v;  // w in 0..7, 2 warps per k
        }
        __syncthreads();
        if (t < 256) {
            int k = t >> 6;
            float n = nrm_part[2 * k] + nrm_part[2 * k + 1];
            float f = n / ((1.0f + n) * sqrtf(n + 1e-9f));  // squash factor
            capsm[t] = cval * f;
        }
        __syncthreads();

        if (it < 2) {
            // cw[k][s] += dot_d(hat[k][s][:], cap[k][:]); 8 warps per k
            int k = w >> 3;
            int s0 = w & 7;
            float c0 = capsm[k * DD + lane];
            float c1 = capsm[k * DD + 32 + lane];
            for (int s2 = s0; s2 < SS; s2 += 8) {
                const float* hrow = hat_s + (k * SS + s2) * DD;
                float v = hrow[lane] * c0 + hrow[32 + lane] * c1;
                #pragma unroll
                for (int off = 16; off > 0; off >>= 1)
                    v += __shfl_xor_sync(0xffffffffu, v, off);
                if (lane == 0) cw[k * SS + s2] += v;
            }
            __syncthreads();
        } else {
            if (t < 256) out_cap[(size_t)b * 256 + t] = capsm[t];
        }
    }
}

// ---------------- launch -------------------------------------------------------
extern "C" void kernel_launch(void* const* d_in, const int* in_sizes, int n_in,
                              void* d_out, int out_size) {
    const int* uid = (const int*)d_in[0];
    const int* age = (const int*)d_in[1];
    const int* gender = (const int*)d_in[2];
    const int* occup = (const int*)d_in[3];
    const int* mid_his = (const int*)d_in[4];
    const float* mask = (const float*)d_in[5];
    const float* user_emb = (const float*)d_in[6];
    const float* age_tab = (const float*)d_in[7];
    const float* gender_tab = (const float*)d_in[8];
    const float* occup_tab = (const float*)d_in[9];
    const float* mid_emb = (const float*)d_in[10];
    const float* w_capsule = (const float*)d_in[11];

    float* out = (float*)d_out;
    float* out_cap = out;                         // [B, NI, D]
    float* out_adj = out + (size_t)BB * NI * DD;  // [B, S, S]

    const int ADJ_SMEM = (2 * 64 * AS + 64 + AS) * 4;  // 115840 B
    const int HAT_SMEM = (64 * 128 + 64 * 256) * 4;    // 98304 B
    const int ROUTE_SMEM = (NI * SS * DD + 2 * NI * SS + 1024 + 256 + 8 + 200) * 4;  // 217152 B

    cudaFuncSetAttribute(adj_kernel, cudaFuncAttributeMaxDynamicSharedMemorySize, ADJ_SMEM);
    cudaFuncSetAttribute(hat_kernel, cudaFuncAttributeMaxDynamicSharedMemorySize, HAT_SMEM);
    cudaFuncSetAttribute(route_kernel, cudaFuncAttributeMaxDynamicSharedMemorySize, ROUTE_SMEM);

    // order: hat -> route (dependency), adj last (independent) — also rotates
    // which kernel lands in the fixed ncu capture slot for attribution.
    hat_kernel<<<dim3(8, 200), 512, HAT_SMEM>>>(mid_his, mask, mid_emb, w_capsule);
    route_kernel<<<BB, RT, ROUTE_SMEM>>>(mask, out_cap);
    adj_kernel<<<BB, ADJ_T, ADJ_SMEM>>>(uid, age, gender, occup, user_emb, age_tab,
                                        gender_tab, occup_tab, mid_his, mask, mid_emb,
                                        out_adj);
}

// round 8
// speedup vs baseline: 1.1279x; 1.0659x over previous
#include <cuda_runtime.h>
#include <math.h>

#define BB 1024
#define SS 200
#define DD 64
#define NI 4
#define AS 224    // padded S for adj tiling
#define RP 68     // padded row length (floats) for row-major d-vectorized tiles

// ---------------- scratch (__device__ globals: allocation-free) ----------------
__device__ float g_hat_buf[(size_t)BB * NI * SS * DD];   // [b][k][s][d], 210MB

// ---------------- f32x2 helpers (packed fp32 FMA: 2x fp32 throughput) ----------
static __device__ __forceinline__ unsigned long long pk2(float lo, float hi) {
    unsigned long long r;
    asm("mov.b64 %0, {%1, %2};" : "=l"(r) : "f"(lo), "f"(hi));
    return r;
}
static __device__ __forceinline__ float2 upk2(unsigned long long v) {
    float2 f;
    asm("mov.b64 {%0, %1}, %2;" : "=f"(f.x), "=f"(f.y) : "l"(v));
    return f;
}
static __device__ __forceinline__ unsigned long long fma2(unsigned long long a,
                                                          unsigned long long b,
                                                          unsigned long long c) {
    unsigned long long d;
    asm("fma.rn.f32x2 %0, %1, %2, %3;" : "=l"(d) : "l"(a), "l"(b), "l"(c));
    return d;
}
static __device__ __forceinline__ float fast_sigmoid(float x) {
    return __fdividef(1.0f, 1.0f + __expf(-x));
}

// ---------------- K1: adj v3 — symmetric tiles, 2 threads/tile, d-vectorized ---
// 544 threads; slot = t>>1 in [0,272), half = t&1.
// Tile (I,J): triangular inversion J(J+1)<=slot<(J+1)(J+2), I = slot-J(J+1),
// rows [7I,7I+7) split half0: rows 0-3, half1: rows 4-6; cols [14J,14J+14).
// Each output cell written exactly once (normal iff i<=j, transposed iff i<j).
#define ADJ_T 544
__global__ __launch_bounds__(ADJ_T) void adj_kernel(const int* __restrict__ uid,
                                                    const int* __restrict__ age,
                                                    const int* __restrict__ gender,
                                                    const int* __restrict__ occup,
                                                    const float* __restrict__ ue,
                                                    const float* __restrict__ at,
                                                    const float* __restrict__ gt,
                                                    const float* __restrict__ ot,
                                                    const int* __restrict__ mid_his,
                                                    const float* __restrict__ mask,
                                                    const float* __restrict__ mid_emb,
                                                    float* __restrict__ out_adj) {
    extern __shared__ float sm[];
    float* it_t = sm;                    // [64][AS] col-major (for bv LDS.64)
    float* hu_r = it_t + 64 * AS;        // [AS][RP] row-major (it*u, for av LDS.128)
    float* u_sm = hu_r + AS * RP;        // [64]
    float* m_sm = u_sm + 64;             // [AS]

    int b = blockIdx.x;
    int t = threadIdx.x;

    if (t < 64) {
        float v = ue[(size_t)uid[b] * DD + t] + gt[(size_t)gender[b] * DD + t] +
                  at[(size_t)age[b] * DD + t] + ot[(size_t)occup[b] * DD + t];
        u_sm[t] = 0.25f * v;
    }
    for (int s = t; s < AS; s += ADJ_T) m_sm[s] = (s < SS) ? mask[b * SS + s] : 0.f;
    __syncthreads();   // u_sm ready before hu_r writes

    const float4* emb4 = (const float4*)mid_emb;
    for (int idx = t; idx < 16 * AS; idx += ADJ_T) {
        int d4 = idx / AS;
        int s = idx - d4 * AS;
        float4 v = make_float4(0.f, 0.f, 0.f, 0.f);
        if (s < SS) {
            int mid = mid_his[b * SS + s];
            float m = mask[b * SS + s];
            float4 e = emb4[(size_t)mid * 16 + d4];
            v.x = e.x * m; v.y = e.y * m; v.z = e.z * m; v.w = e.w * m;
        }
        int d0 = 4 * d4;
        it_t[(d0 + 0) * AS + s] = v.x;
        it_t[(d0 + 1) * AS + s] = v.y;
        it_t[(d0 + 2) * AS + s] = v.z;
        it_t[(d0 + 3) * AS + s] = v.w;
        float4 hv;
        hv.x = v.x * u_sm[d0 + 0];
        hv.y = v.y * u_sm[d0 + 1];
        hv.z = v.z * u_sm[d0 + 2];
        hv.w = v.w * u_sm[d0 + 3];
        *(float4*)(hu_r + s * RP + d0) = hv;
    }
    __syncthreads();

    if (t < 2 * 272) {
        int slot = t >> 1;
        int half = t & 1;
        int J = (int)((sqrtf((float)(4 * slot + 1)) - 1.0f) * 0.5f);
        while ((J + 1) * (J + 2) <= slot) ++J;
        while (J * (J + 1) > slot) --J;
        int I = slot - J * (J + 1);
        int ib = 7 * I + 4 * half;     // half0: 4 rows, half1: 3 rows (+1 dummy)
        int jb = 14 * J;
        int nr = half ? 3 : 4;

        unsigned long long acc[4][7];
        #pragma unroll
        for (int ii = 0; ii < 4; ii++)
            #pragma unroll
            for (int jj = 0; jj < 7; jj++) acc[ii][jj] = 0ull;

        for (int d0 = 0; d0 < 64; d0 += 4) {
            float4 av4[4];
            #pragma unroll
            for (int ii = 0; ii < 4; ii++)
                av4[ii] = *(const float4*)(hu_r + (ib + ii) * RP + d0);
            #pragma unroll
            for (int dd = 0; dd < 4; dd++) {
                const float* irow = it_t + (d0 + dd) * AS;
                unsigned long long bv[7];
                #pragma unroll
                for (int jj = 0; jj < 7; jj++)
                    bv[jj] = *(const unsigned long long*)(irow + jb + 2 * jj);
                #pragma unroll
                for (int ii = 0; ii < 4; ii++) {
                    const float* ap = (const float*)&av4[ii];
                    float a = ap[dd];
                    unsigned long long av = pk2(a, a);
                    #pragma unroll
                    for (int jj = 0; jj < 7; jj++)
                        acc[ii][jj] = fma2(av, bv[jj], acc[ii][jj]);
                }
            }
        }

        float* ob = out_adj + (size_t)b * (SS * SS);
        #pragma unroll
        for (int ii = 0; ii < 4; ii++) {
            if (ii < nr) {
                int i = ib + ii;
                if (i < SS) {
                    float mi = m_sm[i];
                    #pragma unroll
                    for (int jj = 0; jj < 7; jj++) {
                        int j = jb + 2 * jj;
                        if (j < SS) {   // j even, SS even -> j+1 < SS too
                            float2 x = upk2(acc[ii][jj]);
                            float xv = mi * m_sm[j] * fast_sigmoid(x.x);
                            float yv = mi * m_sm[j + 1] * fast_sigmoid(x.y);
                            if (i <= j) {
                                float2 o; o.x = xv; o.y = yv;
                                *(float2*)(ob + (size_t)i * SS + j) = o;
                            } else if (i == j + 1) {
                                ob[(size_t)i * SS + j + 1] = yv;
                            }
                            if (i < j) {
                                ob[(size_t)j * SS + i] = xv;
                                ob[(size_t)(j + 1) * SS + i] = yv;
                            } else if (i == j) {
                                ob[(size_t)(j + 1) * SS + i] = yv;
                            }
                        }
                    }
                }
            }
        }
    }
}

// ---------------- K2: hat v2 — row-major it (d-vectorized av), 512 threads -----
// Stores directly in routing layout g_hat[b][k][s][d].
__global__ __launch_bounds__(512) void hat_kernel(const int* __restrict__ mid_his,
                                                  const float* __restrict__ mask,
                                                  const float* __restrict__ mid_emb,
                                                  const float* __restrict__ w_capsule) {
    extern __shared__ float sm[];
    float* it_r = sm;                 // [128][RP] row-major
    float* w_t = it_r + 128 * RP;     // [64][256] col-major

    int s = blockIdx.y;
    int b0 = blockIdx.x * 128;
    int t = threadIdx.x;

    const float4* emb4 = (const float4*)mid_emb;
    const float4* w4 = (const float4*)w_capsule;

    for (int idx = t; idx < 16 * 128; idx += 512) {
        int d4 = idx >> 7, bl = idx & 127;
        int gb = b0 + bl;
        int mid = mid_his[gb * SS + s];
        float m = mask[gb * SS + s];
        float4 e = emb4[(size_t)mid * 16 + d4];
        float4 v;
        v.x = e.x * m; v.y = e.y * m; v.z = e.z * m; v.w = e.w * m;
        *(float4*)(it_r + bl * RP + 4 * d4) = v;
    }
    for (int idx = t; idx < 16 * 256; idx += 512) {
        int d4 = idx >> 8, e = idx & 255;
        float4 v = w4[((size_t)s * 256 + e) * 16 + d4];
        w_t[(4 * d4 + 0) * 256 + e] = v.x;
        w_t[(4 * d4 + 1) * 256 + e] = v.y;
        w_t[(4 * d4 + 2) * 256 + e] = v.z;
        w_t[(4 * d4 + 3) * 256 + e] = v.w;
    }
    __syncthreads();

    int tx = t & 31, ty = t >> 5;  // tx: e-pairs, ty (warp): b-row base
    unsigned long long acc[8][4];
    #pragma unroll
    for (int ii = 0; ii < 8; ii++)
        #pragma unroll
        for (int jj = 0; jj < 4; jj++) acc[ii][jj] = 0ull;

    for (int d0 = 0; d0 < 64; d0 += 4) {
        float4 av4[8];
        #pragma unroll
        for (int ii = 0; ii < 8; ii++)
            av4[ii] = *(const float4*)(it_r + (ty + 16 * ii) * RP + d0);  // broadcast
        #pragma unroll
        for (int dd = 0; dd < 4; dd++) {
            const float* wr = w_t + (d0 + dd) * 256;
            unsigned long long bv[4];
            #pragma unroll
            for (int jj = 0; jj < 4; jj++)
                bv[jj] = *(const unsigned long long*)(wr + 2 * tx + 64 * jj);
            #pragma unroll
            for (int ii = 0; ii < 8; ii++) {
                const float* ap = (const float*)&av4[ii];
                float a = ap[dd];
                unsigned long long av = pk2(a, a);
                #pragma unroll
                for (int jj = 0; jj < 4; jj++)
                    acc[ii][jj] = fma2(av, bv[jj], acc[ii][jj]);
            }
        }
    }

    // e = 2*tx + 64*jj  ->  k = jj, dd = 2*tx
    #pragma unroll
    for (int ii = 0; ii < 8; ii++) {
        int gb = b0 + ty + 16 * ii;
        #pragma unroll
        for (int jj = 0; jj < 4; jj++) {
            float2 v = upk2(acc[ii][jj]);
            *(float2*)(g_hat_buf + (((size_t)gb * NI + jj) * SS + s) * DD + 2 * tx) = v;
        }
    }
}

// ---------------- K3: routing v2 — 1024 threads, wide phases, shuffle reduces ---
#define RT 1024
__global__ __launch_bounds__(RT) void route_kernel(const float* __restrict__ mask,
                                                   float* __restrict__ out_cap) {
    extern __shared__ float sm[];
    float* hat_s    = sm;                  // 51200
    float* cw       = hat_s + NI * SS * DD;  // 800
    float* swm      = cw + NI * SS;          // 800
    float* cap_part = swm + NI * SS;         // 1024
    float* capsm    = cap_part + 1024;       // 256
    float* nrm_part = capsm + 256;           // 8
    float* msk      = nrm_part + 8;          // 200

    int b = blockIdx.x;
    int t = threadIdx.x;
    int lane = t & 31, w = t >> 5;

    const float4* src = (const float4*)(g_hat_buf + (size_t)b * NI * SS * DD);
    float4* dst = (float4*)hat_s;
    for (int i = t; i < NI * SS * DD / 4; i += RT) dst[i] = src[i];
    if (t < NI * SS) cw[t] = 0.f;
    if (t >= 800 && t < 800 + SS) msk[t - 800] = mask[b * SS + (t - 800)];
    __syncthreads();

    for (int it = 0; it < 3; it++) {
        if (t < SS) {
            float c0 = cw[0 * SS + t], c1 = cw[1 * SS + t];
            float c2 = cw[2 * SS + t], c3 = cw[3 * SS + t];
            float mx = fmaxf(fmaxf(c0, c1), fmaxf(c2, c3));
            float e0 = __expf(c0 - mx), e1 = __expf(c1 - mx);
            float e2 = __expf(c2 - mx), e3 = __expf(c3 - mx);
            float inv = __fdividef(1.0f, e0 + e1 + e2 + e3);
            float z = (msk[t] != 0.f) ? inv : 0.f;
            swm[0 * SS + t] = e0 * z;
            swm[1 * SS + t] = e1 * z;
            swm[2 * SS + t] = e2 * z;
            swm[3 * SS + t] = e3 * z;
        }
        __syncthreads();

        {
            int part = t >> 8;
            int r = t & 255;
            int k = r >> 6, d = r & 63;
            const float* hp = hat_s + (k * SS + part * 50) * DD + d;
            const float* sp = swm + k * SS + part * 50;
            float acc = 0.f;
            #pragma unroll 5
            for (int s2 = 0; s2 < 50; s2++) acc = fmaf(sp[s2], hp[s2 * DD], acc);
            cap_part[part * 256 + r] = acc;
        }
        __syncthreads();

        float cval = 0.f;
        if (t < 256) {
            cval = cap_part[t] + cap_part[256 + t] + cap_part[512 + t] + cap_part[768 + t];
            float v = cval * cval;
            #pragma unroll
            for (int off = 16; off > 0; off >>= 1)
                v += __shfl_xor_sync(0xffffffffu, v, off);
            if (lane == 0) nrm_part[w] = v;
        }
        __syncthreads();
        if (t < 256) {
            int k = t >> 6;
            float n = nrm_part[2 * k] + nrm_part[2 * k + 1];
            float f = n / ((1.0f + n) * sqrtf(n + 1e-9f));
            capsm[t] = cval * f;
        }
        __syncthreads();

        if (it < 2) {
            int k = w >> 3;
            int s0 = w & 7;
            float c0 = capsm[k * DD + lane];
            float c1 = capsm[k * DD + 32 + lane];
            for (int s2 = s0; s2 < SS; s2 += 8) {
                const float* hrow = hat_s + (k * SS + s2) * DD;
                float v = hrow[lane] * c0 + hrow[32 + lane] * c1;
                #pragma unroll
                for (int off = 16; off > 0; off >>= 1)
                    v += __shfl_xor_sync(0xffffffffu, v, off);
                if (lane == 0) cw[k * SS + s2] += v;
            }
            __syncthreads();
        } else {
            if (t < 256) out_cap[(size_t)b * 256 + t] = capsm[t];
        }
    }
}

// ---------------- launch -------------------------------------------------------
extern "C" void kernel_launch(void* const* d_in, const int* in_sizes, int n_in,
                              void* d_out, int out_size) {
    const int* uid = (const int*)d_in[0];
    const int* age = (const int*)d_in[1];
    const int* gender = (const int*)d_in[2];
    const int* occup = (const int*)d_in[3];
    const int* mid_his = (const int*)d_in[4];
    const float* mask = (const float*)d_in[5];
    const float* user_emb = (const float*)d_in[6];
    const float* age_tab = (const float*)d_in[7];
    const float* gender_tab = (const float*)d_in[8];
    const float* occup_tab = (const float*)d_in[9];
    const float* mid_emb = (const float*)d_in[10];
    const float* w_capsule = (const float*)d_in[11];

    float* out = (float*)d_out;
    float* out_cap = out;                         // [B, NI, D]
    float* out_adj = out + (size_t)BB * NI * DD;  // [B, S, S]

    const int ADJ_SMEM = (64 * AS + AS * RP + 64 + AS) * 4;   // 119424 B
    const int HAT_SMEM = (128 * RP + 64 * 256) * 4;           // 100352 B
    const int ROUTE_SMEM = (NI * SS * DD + 2 * NI * SS + 1024 + 256 + 8 + 200) * 4;  // 217152 B

    cudaFuncSetAttribute(adj_kernel, cudaFuncAttributeMaxDynamicSharedMemorySize, ADJ_SMEM);
    cudaFuncSetAttribute(hat_kernel, cudaFuncAttributeMaxDynamicSharedMemorySize, HAT_SMEM);
    cudaFuncSetAttribute(route_kernel, cudaFuncAttributeMaxDynamicSharedMemorySize, ROUTE_SMEM);

    hat_kernel<<<dim3(8, 200), 512, HAT_SMEM>>>(mid_his, mask, mid_emb, w_capsule);
    route_kernel<<<BB, RT, ROUTE_SMEM>>>(mask, out_cap);
    adj_kernel<<<BB, ADJ_T, ADJ_SMEM>>>(uid, age, gender, occup, user_emb, age_tab,
                                        gender_tab, occup_tab, mid_his, mask, mid_emb,
                                        out_adj);
}

// round 16
// speedup vs baseline: 1.1921x; 1.0569x over previous
#include <cuda_runtime.h>
#include <math.h>

#define BB 1024
#define SS 200
#define DD 64
#define NI 4
#define AS 224    // padded S for adj tiling
#define RP 68     // padded row length (floats) for row-major d-vectorized tiles

// ---------------- scratch (__device__ globals: allocation-free) ----------------
__device__ float g_hat_buf[(size_t)BB * NI * SS * DD];   // [b][k][s][d], 210MB

// ---------------- f32x2 helpers (packed fp32 FMA: 2x fp32 throughput) ----------
static __device__ __forceinline__ unsigned long long pk2(float lo, float hi) {
    unsigned long long r;
    asm("mov.b64 %0, {%1, %2};" : "=l"(r) : "f"(lo), "f"(hi));
    return r;
}
static __device__ __forceinline__ float2 upk2(unsigned long long v) {
    float2 f;
    asm("mov.b64 {%0, %1}, %2;" : "=f"(f.x), "=f"(f.y) : "l"(v));
    return f;
}
static __device__ __forceinline__ unsigned long long fma2(unsigned long long a,
                                                          unsigned long long b,
                                                          unsigned long long c) {
    unsigned long long d;
    asm("fma.rn.f32x2 %0, %1, %2, %3;" : "=l"(d) : "l"(a), "l"(b), "l"(c));
    return d;
}
static __device__ __forceinline__ float fast_sigmoid(float x) {
    return __fdividef(1.0f, 1.0f + __expf(-x));
}

// ---------------- K1: adj v4 — symmetric tiles, 1 thread/tile x 2 halves, ------
// 2 CTAs/SM. 288 threads; tile t<272 -> (I,J) triangular inversion; thread runs
// row-halves (rows 0-3, rows 4-6) sequentially with acc[4][7] reused.
// Each output cell written exactly once (normal iff i<=j, transposed iff i<j).
#define ADJ_T 288
__global__ __launch_bounds__(ADJ_T, 2) void adj_kernel(const int* __restrict__ uid,
                                                       const int* __restrict__ age,
                                                       const int* __restrict__ gender,
                                                       const int* __restrict__ occup,
                                                       const float* __restrict__ ue,
                                                       const float* __restrict__ at,
                                                       const float* __restrict__ gt,
                                                       const float* __restrict__ ot,
                                                       const int* __restrict__ mid_his,
                                                       const float* __restrict__ mask,
                                                       const float* __restrict__ mid_emb,
                                                       float* __restrict__ out_adj) {
    extern __shared__ float sm[];
    float* it_t = sm;               // [64][AS] col-major (masked item_his)
    float* u_sm = it_t + 64 * AS;   // [64]
    float* m_sm = u_sm + 64;        // [AS]

    int b = blockIdx.x;
    int t = threadIdx.x;

    if (t < 64) {
        float v = ue[(size_t)uid[b] * DD + t] + gt[(size_t)gender[b] * DD + t] +
                  at[(size_t)age[b] * DD + t] + ot[(size_t)occup[b] * DD + t];
        u_sm[t] = 0.25f * v;
    }
    for (int s = t; s < AS; s += ADJ_T) m_sm[s] = (s < SS) ? mask[b * SS + s] : 0.f;

    const float4* emb4 = (const float4*)mid_emb;
    for (int idx = t; idx < 16 * AS; idx += ADJ_T) {
        int d4 = idx / AS;
        int s = idx - d4 * AS;
        float4 v = make_float4(0.f, 0.f, 0.f, 0.f);
        if (s < SS) {
            int mid = mid_his[b * SS + s];
            float m = mask[b * SS + s];
            float4 e = emb4[(size_t)mid * 16 + d4];
            v.x = e.x * m; v.y = e.y * m; v.z = e.z * m; v.w = e.w * m;
        }
        int d0 = 4 * d4;
        it_t[(d0 + 0) * AS + s] = v.x;
        it_t[(d0 + 1) * AS + s] = v.y;
        it_t[(d0 + 2) * AS + s] = v.z;
        it_t[(d0 + 3) * AS + s] = v.w;
    }
    __syncthreads();

    if (t < 272) {
        int J = (int)((sqrtf((float)(4 * t + 1)) - 1.0f) * 0.5f);
        while ((J + 1) * (J + 2) <= t) ++J;
        while (J * (J + 1) > t) --J;
        int I = t - J * (J + 1);
        int jb = 14 * J;
        float* ob = out_adj + (size_t)b * (SS * SS);

        for (int half = 0; half < 2; half++) {
            int ib = 7 * I + 4 * half;   // half0: rows 0-3, half1: rows 4-6
            int nr = half ? 3 : 4;

            unsigned long long acc[4][7];
            #pragma unroll
            for (int ii = 0; ii < 4; ii++)
                #pragma unroll
                for (int jj = 0; jj < 7; jj++) acc[ii][jj] = 0ull;

            #pragma unroll 4
            for (int d = 0; d < 64; d++) {
                const float* row = it_t + d * AS;
                float ud = u_sm[d];
                unsigned long long bv[7];
                #pragma unroll
                for (int jj = 0; jj < 7; jj++)
                    bv[jj] = *(const unsigned long long*)(row + jb + 2 * jj);
                #pragma unroll
                for (int ii = 0; ii < 4; ii++) {
                    float a = row[ib + ii] * ud;
                    unsigned long long av = pk2(a, a);
                    #pragma unroll
                    for (int jj = 0; jj < 7; jj++)
                        acc[ii][jj] = fma2(av, bv[jj], acc[ii][jj]);
                }
            }

            #pragma unroll
            for (int ii = 0; ii < 4; ii++) {
                if (ii < nr) {
                    int i = ib + ii;
                    if (i < SS) {
                        float mi = m_sm[i];
                        #pragma unroll
                        for (int jj = 0; jj < 7; jj++) {
                            int j = jb + 2 * jj;
                            if (j < SS) {   // j even, SS even -> j+1 < SS too
                                float2 x = upk2(acc[ii][jj]);
                                float xv = mi * m_sm[j] * fast_sigmoid(x.x);
                                float yv = mi * m_sm[j + 1] * fast_sigmoid(x.y);
                                if (i <= j) {
                                    float2 o; o.x = xv; o.y = yv;
                                    *(float2*)(ob + (size_t)i * SS + j) = o;
                                } else if (i == j + 1) {
                                    ob[(size_t)i * SS + j + 1] = yv;
                                }
                                if (i < j) {
                                    ob[(size_t)j * SS + i] = xv;
                                    ob[(size_t)(j + 1) * SS + i] = yv;
                                } else if (i == j) {
                                    ob[(size_t)(j + 1) * SS + i] = yv;
                                }
                            }
                        }
                    }
                }
            }
        }
    }
}

// ---------------- K2: hat v3 — 64-row b-tile, 2 CTAs/SM, 32 warps/SM -----------
// grid (16, 200); 512 threads; per-thread tile 4 b-rows x 4 e-pairs.
// Stores directly in routing layout g_hat[b][k][s][d].
__global__ __launch_bounds__(512, 2) void hat_kernel(const int* __restrict__ mid_his,
                                                     const float* __restrict__ mask,
                                                     const float* __restrict__ mid_emb,
                                                     const float* __restrict__ w_capsule) {
    extern __shared__ float sm[];
    float* it_r = sm;                // [64][RP] row-major (b-rows x d)
    float* w_t = it_r + 64 * RP;     // [64][256] col-major (d x e)

    int s = blockIdx.y;
    int b0 = blockIdx.x * 64;
    int t = threadIdx.x;

    const float4* emb4 = (const float4*)mid_emb;
    const float4* w4 = (const float4*)w_capsule;

    for (int idx = t; idx < 16 * 64; idx += 512) {
        int d4 = idx >> 6, bl = idx & 63;
        int gb = b0 + bl;
        int mid = mid_his[gb * SS + s];
        float m = mask[gb * SS + s];
        float4 e = emb4[(size_t)mid * 16 + d4];
        float4 v;
        v.x = e.x * m; v.y = e.y * m; v.z = e.z * m; v.w = e.w * m;
        *(float4*)(it_r + bl * RP + 4 * d4) = v;
    }
    for (int idx = t; idx < 16 * 256; idx += 512) {
        int d4 = idx >> 8, e = idx & 255;
        float4 v = w4[((size_t)s * 256 + e) * 16 + d4];
        w_t[(4 * d4 + 0) * 256 + e] = v.x;
        w_t[(4 * d4 + 1) * 256 + e] = v.y;
        w_t[(4 * d4 + 2) * 256 + e] = v.z;
        w_t[(4 * d4 + 3) * 256 + e] = v.w;
    }
    __syncthreads();

    int tx = t & 31, ty = t >> 5;   // tx: e-pair, ty (0..15): b-row base
    unsigned long long acc[4][4];
    #pragma unroll
    for (int ii = 0; ii < 4; ii++)
        #pragma unroll
        for (int jj = 0; jj < 4; jj++) acc[ii][jj] = 0ull;

    for (int d0 = 0; d0 < 64; d0 += 4) {
        float4 av4[4];
        #pragma unroll
        for (int ii = 0; ii < 4; ii++)
            av4[ii] = *(const float4*)(it_r + (ty + 16 * ii) * RP + d0);  // bcast
        #pragma unroll
        for (int dd = 0; dd < 4; dd++) {
            const float* wr = w_t + (d0 + dd) * 256;
            unsigned long long bv[4];
            #pragma unroll
            for (int jj = 0; jj < 4; jj++)
                bv[jj] = *(const unsigned long long*)(wr + 2 * tx + 64 * jj);
            #pragma unroll
            for (int ii = 0; ii < 4; ii++) {
                const float* ap = (const float*)&av4[ii];
                float a = ap[dd];
                unsigned long long av = pk2(a, a);
                #pragma unroll
                for (int jj = 0; jj < 4; jj++)
                    acc[ii][jj] = fma2(av, bv[jj], acc[ii][jj]);
            }
        }
    }

    // e = 2*tx + 64*jj -> k = jj, dd = 2*tx
    #pragma unroll
    for (int ii = 0; ii < 4; ii++) {
        int gb = b0 + ty + 16 * ii;
        #pragma unroll
        for (int jj = 0; jj < 4; jj++) {
            float2 v = upk2(acc[ii][jj]);
            *(float2*)(g_hat_buf + (((size_t)gb * NI + jj) * SS + s) * DD + 2 * tx) = v;
        }
    }
}

// ---------------- K3: routing v2 — 1024 threads, wide phases, shuffle reduces ---
#define RT 1024
__global__ __launch_bounds__(RT) void route_kernel(const float* __restrict__ mask,
                                                   float* __restrict__ out_cap) {
    extern __shared__ float sm[];
    float* hat_s    = sm;                  // 51200
    float* cw       = hat_s + NI * SS * DD;  // 800
    float* swm      = cw + NI * SS;          // 800
    float* cap_part = swm + NI * SS;         // 1024
    float* capsm    = cap_part + 1024;       // 256
    float* nrm_part = capsm + 256;           // 8
    float* msk      = nrm_part + 8;          // 200

    int b = blockIdx.x;
    int t = threadIdx.x;
    int lane = t & 31, w = t >> 5;

    const float4* src = (const float4*)(g_hat_buf + (size_t)b * NI * SS * DD);
    float4* dst = (float4*)hat_s;
    for (int i = t; i < NI * SS * DD / 4; i += RT) dst[i] = src[i];
    if (t < NI * SS) cw[t] = 0.f;
    if (t >= 800 && t < 800 + SS) msk[t - 800] = mask[b * SS + (t - 800)];
    __syncthreads();

    for (int it = 0; it < 3; it++) {
        if (t < SS) {
            float c0 = cw[0 * SS + t], c1 = cw[1 * SS + t];
            float c2 = cw[2 * SS + t], c3 = cw[3 * SS + t];
            float mx = fmaxf(fmaxf(c0, c1), fmaxf(c2, c3));
            float e0 = __expf(c0 - mx), e1 = __expf(c1 - mx);
            float e2 = __expf(c2 - mx), e3 = __expf(c3 - mx);
            float inv = __fdividef(1.0f, e0 + e1 + e2 + e3);
            float z = (msk[t] != 0.f) ? inv : 0.f;
            swm[0 * SS + t] = e0 * z;
            swm[1 * SS + t] = e1 * z;
            swm[2 * SS + t] = e2 * z;
            swm[3 * SS + t] = e3 * z;
        }
        __syncthreads();

        {
            int part = t >> 8;
            int r = t & 255;
            int k = r >> 6, d = r & 63;
            const float* hp = hat_s + (k * SS + part * 50) * DD + d;
            const float* sp = swm + k * SS + part * 50;
            float acc = 0.f;
            #pragma unroll 5
            for (int s2 = 0; s2 < 50; s2++) acc = fmaf(sp[s2], hp[s2 * DD], acc);
            cap_part[part * 256 + r] = acc;
        }
        __syncthreads();

        float cval = 0.f;
        if (t < 256) {
            cval = cap_part[t] + cap_part[256 + t] + cap_part[512 + t] + cap_part[768 + t];
            float v = cval * cval;
            #pragma unroll
            for (int off = 16; off > 0; off >>= 1)
                v += __shfl_xor_sync(0xffffffffu, v, off);
            if (lane == 0) nrm_part[w] = v;
        }
        __syncthreads();
        if (t < 256) {
            int k = t >> 6;
            float n = nrm_part[2 * k] + nrm_part[2 * k + 1];
            float f = n / ((1.0f + n) * sqrtf(n + 1e-9f));
            capsm[t] = cval * f;
        }
        __syncthreads();

        if (it < 2) {
            int k = w >> 3;
            int s0 = w & 7;
            float c0 = capsm[k * DD + lane];
            float c1 = capsm[k * DD + 32 + lane];
            for (int s2 = s0; s2 < SS; s2 += 8) {
                const float* hrow = hat_s + (k * SS + s2) * DD;
                float v = hrow[lane] * c0 + hrow[32 + lane] * c1;
                #pragma unroll
                for (int off = 16; off > 0; off >>= 1)
                    v += __shfl_xor_sync(0xffffffffu, v, off);
                if (lane == 0) cw[k * SS + s2] += v;
            }
            __syncthreads();
        } else {
            if (t < 256) out_cap[(size_t)b * 256 + t] = capsm[t];
        }
    }
}

// ---------------- launch -------------------------------------------------------
extern "C" void kernel_launch(void* const* d_in, const int* in_sizes, int n_in,
                              void* d_out, int out_size) {
    const int* uid = (const int*)d_in[0];
    const int* age = (const int*)d_in[1];
    const int* gender = (const int*)d_in[2];
    const int* occup = (const int*)d_in[3];
    const int* mid_his = (const int*)d_in[4];
    const float* mask = (const float*)d_in[5];
    const float* user_emb = (const float*)d_in[6];
    const float* age_tab = (const float*)d_in[7];
    const float* gender_tab = (const float*)d_in[8];
    const float* occup_tab = (const float*)d_in[9];
    const float* mid_emb = (const float*)d_in[10];
    const float* w_capsule = (const float*)d_in[11];

    float* out = (float*)d_out;
    float* out_cap = out;                         // [B, NI, D]
    float* out_adj = out + (size_t)BB * NI * DD;  // [B, S, S]

    const int ADJ_SMEM = (64 * AS + 64 + AS + 16) * 4;   // 58560 B -> 2 CTAs/SM
    const int HAT_SMEM = (64 * RP + 64 * 256) * 4;       // 82944 B -> 2 CTAs/SM
    const int ROUTE_SMEM = (NI * SS * DD + 2 * NI * SS + 1024 + 256 + 8 + 200) * 4;  // 217152 B

    cudaFuncSetAttribute(adj_kernel, cudaFuncAttributeMaxDynamicSharedMemorySize, ADJ_SMEM);
    cudaFuncSetAttribute(hat_kernel, cudaFuncAttributeMaxDynamicSharedMemorySize, HAT_SMEM);
    cudaFuncSetAttribute(route_kernel, cudaFuncAttributeMaxDynamicSharedMemorySize, ROUTE_SMEM);

    hat_kernel<<<dim3(16, 200), 512, HAT_SMEM>>>(mid_his, mask, mid_emb, w_capsule);
    route_kernel<<<BB, RT, ROUTE_SMEM>>>(mask, out_cap);
    adj_kernel<<<BB, ADJ_T, ADJ_SMEM>>>(uid, age, gender, occup, user_emb, age_tab,
                                        gender_tab, occup_tab, mid_his, mask, mid_emb,
                                        out_adj);
}